// round 1
// baseline (speedup 1.0000x reference)
#include <cuda_runtime.h>
#include <cstdint>
#include <cstddef>

#define D_MODEL 1024
#define N_HEADS 16
#define HEAD_DIM 64
#define BATCH 4
#define SEQ 2048
#define QKV_STRIDE (3 * D_MODEL)

// Scratch (allocation-free rule: __device__ globals)
__device__ float g_qkv[(size_t)BATCH * SEQ * QKV_STRIDE];   // [b, t, 3*1024]
__device__ float g_attn[(size_t)BATCH * SEQ * D_MODEL];     // [b, t, 1024]

// ---------------------------------------------------------------------------
// GEMM: C[M,N] = A[M,K] @ B[K,N] + bias[N]
// 64x64 block tile, BK=16, 256 threads, 4x4 register micro-tile.
// ---------------------------------------------------------------------------
__global__ void __launch_bounds__(256) gemm_bias_kernel(
    const float* __restrict__ A, const float* __restrict__ B,
    const float* __restrict__ bias, float* __restrict__ C,
    int M, int N, int K)
{
    __shared__ float As[16][68];   // As[k][m]  (pad 4 -> 16B-aligned rows)
    __shared__ float Bs[16][68];   // Bs[k][n]

    const int tid = threadIdx.x;
    const int m0 = blockIdx.y * 64;
    const int n0 = blockIdx.x * 64;
    const int ty = tid >> 4;        // 0..15
    const int tx = tid & 15;        // 0..15

    float acc[4][4] = {};

    const int ar = tid >> 2;          // 0..63 (A row within tile)
    const int ak = (tid & 3) << 2;    // 0,4,8,12 (A k offset)

    for (int k0 = 0; k0 < K; k0 += 16) {
        // Load A tile 64x16 (transposed into As[k][m])
        float4 av = *(const float4*)(A + (size_t)(m0 + ar) * K + k0 + ak);
        As[ak + 0][ar] = av.x;
        As[ak + 1][ar] = av.y;
        As[ak + 2][ar] = av.z;
        As[ak + 3][ar] = av.w;
        // Load B tile 16x64
        float4 bv = *(const float4*)(B + (size_t)(k0 + ty) * N + n0 + (tx << 2));
        *(float4*)&Bs[ty][tx << 2] = bv;
        __syncthreads();

        #pragma unroll
        for (int kk = 0; kk < 16; kk++) {
            float4 a4 = *(const float4*)&As[kk][ty << 2];
            float4 b4 = *(const float4*)&Bs[kk][tx << 2];
            float ae[4] = {a4.x, a4.y, a4.z, a4.w};
            float be[4] = {b4.x, b4.y, b4.z, b4.w};
            #pragma unroll
            for (int i = 0; i < 4; i++)
                #pragma unroll
                for (int j = 0; j < 4; j++)
                    acc[i][j] += ae[i] * be[j];
        }
        __syncthreads();
    }

    #pragma unroll
    for (int i = 0; i < 4; i++) {
        size_t row = (size_t)(m0 + (ty << 2) + i) * N + n0;
        #pragma unroll
        for (int j = 0; j < 4; j++)
            C[row + (tx << 2) + j] = acc[i][j] + bias[n0 + (tx << 2) + j];
    }
}

// ---------------------------------------------------------------------------
// Flash-style causal attention, fp32.
// Grid: (SEQ/64, N_HEADS, BATCH). Block: 256 threads.
// Tiles: BQ=64 q-rows x BKV=64 k-cols, head_dim=64.
// Q/K/V read from g_qkv [b,t,3072] (q:+0, k:+1024, v:+2048), head offset h*64.
// Output written to g_attn in [b, t, h*64+d] layout (ready for out-proj GEMM).
// ---------------------------------------------------------------------------
#define AT_PAD 65
#define AT_SMEM_FLOATS (4 * 64 * AT_PAD + 3 * 64)
#define AT_SMEM_BYTES  (AT_SMEM_FLOATS * 4)

__global__ void __launch_bounds__(256) attn_kernel()
{
    extern __shared__ float sm[];
    float* Qs   = sm;                    // 64 x 65
    float* Ks   = Qs + 64 * AT_PAD;      // 64 x 65
    float* Vs   = Ks + 64 * AT_PAD;      // 64 x 65
    float* Ss   = Vs + 64 * AT_PAD;      // 64 x 65
    float* mrow = Ss + 64 * AT_PAD;      // 64
    float* lrow = mrow + 64;             // 64
    float* arow = lrow + 64;             // 64

    const int tid = threadIdx.x;
    const int q0  = blockIdx.x * 64;
    const int h   = blockIdx.y;
    const int b   = blockIdx.z;
    const float scale = 0.125f;          // 1/sqrt(64)

    const float* qbase = g_qkv + (size_t)b * SEQ * QKV_STRIDE + h * HEAD_DIM;
    const float* kbase = qbase + D_MODEL;
    const float* vbase = qbase + 2 * D_MODEL;

    // Load Q tile (64 rows x 64 d)
    #pragma unroll
    for (int j = 0; j < 4; j++) {
        int idx = tid + j * 256;
        int r = idx >> 4;
        int seg = (idx & 15) << 2;
        float4 v = *(const float4*)(qbase + (size_t)(q0 + r) * QKV_STRIDE + seg);
        Qs[r * AT_PAD + seg + 0] = v.x;
        Qs[r * AT_PAD + seg + 1] = v.y;
        Qs[r * AT_PAD + seg + 2] = v.z;
        Qs[r * AT_PAD + seg + 3] = v.w;
    }
    if (tid < 64) { mrow[tid] = -1e30f; lrow[tid] = 0.0f; }

    const int ty = tid >> 4;
    const int tx = tid & 15;
    const int r0 = ty << 2;
    const int c0 = tx << 2;
    float o[4][4] = {};

    for (int k0 = 0; k0 <= q0; k0 += 64) {
        __syncthreads();   // protect Ks/Vs/Ss reuse across iterations (and Q/m/l init)

        // Load K and V tiles
        #pragma unroll
        for (int j = 0; j < 4; j++) {
            int idx = tid + j * 256;
            int r = idx >> 4;
            int seg = (idx & 15) << 2;
            float4 kv = *(const float4*)(kbase + (size_t)(k0 + r) * QKV_STRIDE + seg);
            Ks[r * AT_PAD + seg + 0] = kv.x;
            Ks[r * AT_PAD + seg + 1] = kv.y;
            Ks[r * AT_PAD + seg + 2] = kv.z;
            Ks[r * AT_PAD + seg + 3] = kv.w;
            float4 vv = *(const float4*)(vbase + (size_t)(k0 + r) * QKV_STRIDE + seg);
            Vs[r * AT_PAD + seg + 0] = vv.x;
            Vs[r * AT_PAD + seg + 1] = vv.y;
            Vs[r * AT_PAD + seg + 2] = vv.z;
            Vs[r * AT_PAD + seg + 3] = vv.w;
        }
        __syncthreads();

        // S = (Q K^T) * scale, causal mask; keep in regs, also write to Ss for row max
        float s[4][4] = {};
        #pragma unroll
        for (int d = 0; d < 64; d++) {
            float a[4], bb[4];
            #pragma unroll
            for (int i = 0; i < 4; i++) a[i]  = Qs[(r0 + i) * AT_PAD + d];
            #pragma unroll
            for (int j = 0; j < 4; j++) bb[j] = Ks[(c0 + j) * AT_PAD + d];
            #pragma unroll
            for (int i = 0; i < 4; i++)
                #pragma unroll
                for (int j = 0; j < 4; j++)
                    s[i][j] += a[i] * bb[j];
        }
        const bool diag = (k0 == q0);
        #pragma unroll
        for (int i = 0; i < 4; i++)
            #pragma unroll
            for (int j = 0; j < 4; j++) {
                float v = s[i][j] * scale;
                if (diag && (k0 + c0 + j > q0 + r0 + i)) v = -1e30f;
                s[i][j] = v;
                Ss[(r0 + i) * AT_PAD + c0 + j] = v;
            }
        __syncthreads();

        // Row max + rescale factor (64 threads)
        if (tid < 64) {
            int r = tid;
            float mo = mrow[r];
            float mx = mo;
            #pragma unroll 8
            for (int c = 0; c < 64; c++) mx = fmaxf(mx, Ss[r * AT_PAD + c]);
            arow[r] = __expf(mo - mx);
            mrow[r] = mx;
        }
        __syncthreads();

        // All threads: p = exp(s - mx), write to Ss; rescale O accumulators
        float al[4], mx4[4];
        #pragma unroll
        for (int i = 0; i < 4; i++) { al[i] = arow[r0 + i]; mx4[i] = mrow[r0 + i]; }
        #pragma unroll
        for (int i = 0; i < 4; i++)
            #pragma unroll
            for (int j = 0; j < 4; j++) {
                float p = __expf(s[i][j] - mx4[i]);
                Ss[(r0 + i) * AT_PAD + c0 + j] = p;
                o[i][j] *= al[i];
            }
        __syncthreads();

        // Row sums -> l update (64 threads, reads only), concurrently O += P @ V
        if (tid < 64) {
            int r = tid;
            float sum = 0.0f;
            #pragma unroll 8
            for (int c = 0; c < 64; c++) sum += Ss[r * AT_PAD + c];
            lrow[r] = lrow[r] * arow[r] + sum;
        }
        #pragma unroll
        for (int k = 0; k < 64; k++) {
            float p[4], vv[4];
            #pragma unroll
            for (int i = 0; i < 4; i++) p[i]  = Ss[(r0 + i) * AT_PAD + k];
            #pragma unroll
            for (int j = 0; j < 4; j++) vv[j] = Vs[k * AT_PAD + c0 + j];
            #pragma unroll
            for (int i = 0; i < 4; i++)
                #pragma unroll
                for (int j = 0; j < 4; j++)
                    o[i][j] += p[i] * vv[j];
        }
    }
    __syncthreads();   // lrow final values visible

    // Epilogue: normalize and write [b, t, h*64 + d]
    float li[4];
    #pragma unroll
    for (int i = 0; i < 4; i++) li[i] = 1.0f / lrow[r0 + i];
    #pragma unroll
    for (int i = 0; i < 4; i++) {
        float* outp = g_attn + ((size_t)b * SEQ + q0 + r0 + i) * D_MODEL + h * HEAD_DIM + c0;
        #pragma unroll
        for (int j = 0; j < 4; j++)
            outp[j] = o[i][j] * li[i];
    }
}

// ---------------------------------------------------------------------------
extern "C" void kernel_launch(void* const* d_in, const int* in_sizes, int n_in,
                              void* d_out, int out_size)
{
    (void)in_sizes; (void)n_in; (void)out_size;
    const float* x     = (const float*)d_in[0];
    const float* w_qkv = (const float*)d_in[1];
    const float* b_qkv = (const float*)d_in[2];
    const float* w_out = (const float*)d_in[3];
    const float* b_out = (const float*)d_in[4];
    float* out = (float*)d_out;

    float* qkv;  cudaGetSymbolAddress((void**)&qkv,  g_qkv);
    float* attn; cudaGetSymbolAddress((void**)&attn, g_attn);

    const int M = BATCH * SEQ;   // 8192

    // 1) QKV projection: [8192,1024] @ [1024,3072] + b_qkv
    gemm_bias_kernel<<<dim3(3 * D_MODEL / 64, M / 64), 256>>>(
        x, w_qkv, b_qkv, qkv, M, 3 * D_MODEL, D_MODEL);

    // 2) Causal attention
    cudaFuncSetAttribute(attn_kernel,
                         cudaFuncAttributeMaxDynamicSharedMemorySize, AT_SMEM_BYTES);
    attn_kernel<<<dim3(SEQ / 64, N_HEADS, BATCH), 256, AT_SMEM_BYTES>>>();

    // 3) Output projection: [8192,1024] @ [1024,1024] + b_out
    gemm_bias_kernel<<<dim3(D_MODEL / 64, M / 64), 256>>>(
        attn, w_out, b_out, out, M, D_MODEL, D_MODEL);
}

// round 4
// speedup vs baseline: 3.6527x; 3.6527x over previous
#include <cuda_runtime.h>
#include <cstdint>
#include <cstddef>

#define D_MODEL 1024
#define N_HEADS 16
#define HEAD_DIM 64
#define BATCH 4
#define SEQ 2048
#define QKV_STRIDE (3 * D_MODEL)

// ------------------------------ scratch ------------------------------------
__device__ float g_qkv[(size_t)BATCH * SEQ * QKV_STRIDE];    // [b,t,3072]
__device__ float g_attn[(size_t)BATCH * SEQ * D_MODEL];      // [b,t,1024]

// ------------------------------ helpers ------------------------------------
__device__ __forceinline__ uint32_t smem_u32(const void* p) {
    uint32_t a;
    asm("{ .reg .u64 t; cvta.to.shared.u64 t, %1; cvt.u32.u64 %0, t; }" : "=r"(a) : "l"(p));
    return a;
}
__device__ __forceinline__ uint32_t f2tf(float x) {
    uint32_t r; asm("cvt.rna.tf32.f32 %0, %1;" : "=r"(r) : "f"(x)); return r;
}
__device__ __forceinline__ void cp16(uint32_t dst, const void* src) {
    asm volatile("cp.async.ca.shared.global [%0], [%1], 16;" :: "r"(dst), "l"(src));
}
#define CP_COMMIT() asm volatile("cp.async.commit_group;" ::: "memory")
#define CP_WAIT0()  asm volatile("cp.async.wait_group 0;" ::: "memory")

// D = A(tf32) * B(tf32) + D ; m16n8k8
__device__ __forceinline__ void mma8(float* c, const uint32_t* a, const uint32_t* b) {
    asm volatile(
        "mma.sync.aligned.m16n8k8.row.col.f32.tf32.tf32.f32 "
        "{%0,%1,%2,%3}, {%4,%5,%6,%7}, {%8,%9}, {%0,%1,%2,%3};"
        : "+f"(c[0]), "+f"(c[1]), "+f"(c[2]), "+f"(c[3])
        : "r"(a[0]), "r"(a[1]), "r"(a[2]), "r"(a[3]), "r"(b[0]), "r"(b[1]));
}

// ------------------------------ tf32 GEMM ----------------------------------
// C[M,N] = A[M,K] @ B[K,N] + bias[N].  128x128 CTA tile, BK=32, 4 warps 64x64.
#define AS_STR 36
#define BS_STR 132
#define G_SMEM ((2 * 128 * AS_STR + 2 * 32 * BS_STR) * 4)

__global__ void __launch_bounds__(128) gemm_mma(
    const float* __restrict__ A, const float* __restrict__ B,
    const float* __restrict__ bias, float* __restrict__ C,
    int M, int N, int K)
{
    extern __shared__ float smf[];
    float* As = smf;                       // [2][128][AS_STR]
    float* Bs = smf + 2 * 128 * AS_STR;    // [2][32][BS_STR]

    const int tid = threadIdx.x;
    const int lane = tid & 31, warp = tid >> 5;
    const int g = lane >> 2, q = lane & 3;
    const int wm = (warp >> 1) * 64, wn = (warp & 1) * 64;
    const int m0 = blockIdx.y * 128, n0 = blockIdx.x * 128;

    // async-copy source/dest
    const float* Ag = A + (size_t)(m0 + tid) * K;                 // one row per thread
    const float* Bg = B + (size_t)(tid >> 2) * N + n0 + ((tid & 3) << 5);
    const uint32_t AsA = smem_u32(As) + tid * AS_STR * 4;
    const uint32_t BsA = smem_u32(Bs) + (tid >> 2) * BS_STR * 4 + ((tid & 3) << 5) * 4;

    float acc[4][8][4];
    #pragma unroll
    for (int i = 0; i < 4; i++)
        #pragma unroll
        for (int j = 0; j < 8; j++)
            #pragma unroll
            for (int t = 0; t < 4; t++) acc[i][j][t] = 0.0f;

    const int nk = K >> 5;

    // prefetch stage 0
    {
        #pragma unroll
        for (int i = 0; i < 8; i++) cp16(AsA + i * 16, Ag + i * 4);
        #pragma unroll
        for (int i = 0; i < 8; i++) cp16(BsA + i * 16, Bg + i * 4);
        CP_COMMIT();
    }

    int buf = 0;
    for (int kt = 0; kt < nk; kt++) {
        CP_WAIT0();
        __syncthreads();
        if (kt + 1 < nk) {
            int s = buf ^ 1;
            const float* ag = Ag + (kt + 1) * 32;
            const float* bg = Bg + (size_t)(kt + 1) * 32 * N;
            uint32_t ad = AsA + s * 128 * AS_STR * 4;
            uint32_t bd = BsA + s * 32 * BS_STR * 4;
            #pragma unroll
            for (int i = 0; i < 8; i++) cp16(ad + i * 16, ag + i * 4);
            #pragma unroll
            for (int i = 0; i < 8; i++) cp16(bd + i * 16, bg + i * 4);
            CP_COMMIT();
        }
        const float* as = As + buf * 128 * AS_STR;
        const float* bs = Bs + buf * 32 * BS_STR;
        #pragma unroll
        for (int kk = 0; kk < 32; kk += 8) {
            uint32_t af[4][4];
            #pragma unroll
            for (int i = 0; i < 4; i++) {
                const float* p = as + (wm + i * 16 + g) * AS_STR + kk + q;
                af[i][0] = f2tf(p[0]);
                af[i][1] = f2tf(p[8 * AS_STR]);
                af[i][2] = f2tf(p[4]);
                af[i][3] = f2tf(p[8 * AS_STR + 4]);
            }
            uint32_t bf[8][2];
            #pragma unroll
            for (int j = 0; j < 8; j++) {
                const float* p = bs + (kk + q) * BS_STR + wn + j * 8 + g;
                bf[j][0] = f2tf(p[0]);
                bf[j][1] = f2tf(p[4 * BS_STR]);
            }
            #pragma unroll
            for (int i = 0; i < 4; i++)
                #pragma unroll
                for (int j = 0; j < 8; j++)
                    mma8(acc[i][j], af[i], bf[j]);
        }
        __syncthreads();
        buf ^= 1;
    }

    // epilogue
    #pragma unroll
    for (int i = 0; i < 4; i++) {
        int row = m0 + wm + i * 16 + g;
        #pragma unroll
        for (int j = 0; j < 8; j++) {
            int col = n0 + wn + j * 8 + 2 * q;
            float b0 = __ldg(&bias[col]), b1 = __ldg(&bias[col + 1]);
            float2 v0 = make_float2(acc[i][j][0] + b0, acc[i][j][1] + b1);
            float2 v1 = make_float2(acc[i][j][2] + b0, acc[i][j][3] + b1);
            *(float2*)(C + (size_t)row * N + col) = v0;
            *(float2*)(C + (size_t)(row + 8) * N + col) = v1;
        }
    }
}

// ------------------------------ attention ----------------------------------
// Flash, BQ=128, BKV=64, 8 warps; warp w owns q-rows [w*16, w*16+16).
#define QS_STR 68
#define A_SMEM ((128 * QS_STR + 64 * QS_STR + 64 * QS_STR + 128 * QS_STR) * 4)

__global__ void __launch_bounds__(256) attn_mma()
{
    extern __shared__ float smf[];
    float* Qs = smf;                   // [128][68] (pre-scaled, tf32)
    float* Ks = Qs + 128 * QS_STR;     // [64][68]  K[kv][d], tf32
    float* Vs = Ks + 64 * QS_STR;      // [64][68]  V[kv][d], tf32
    float* Ps = Vs + 64 * QS_STR;      // [128][68] P[q][kv], tf32 (warp-private rows)

    const int tid = threadIdx.x;
    const int lane = tid & 31, warp = tid >> 5;
    const int g = lane >> 2, q = lane & 3;
    const int q0 = blockIdx.x * 128;
    const int h = blockIdx.y, b = blockIdx.z;

    const float* base = g_qkv + (size_t)b * SEQ * QKV_STRIDE + h * HEAD_DIM;

    // load Q tile (scaled by 1/8, tf32-rounded)
    #pragma unroll
    for (int jj = 0; jj < 8; jj++) {
        int idx = tid + 256 * jj;
        int row = idx >> 4, c4 = (idx & 15) << 2;
        float4 v = *(const float4*)(base + (size_t)(q0 + row) * QKV_STRIDE + c4);
        float* d = Qs + row * QS_STR + c4;
        d[0] = __uint_as_float(f2tf(v.x * 0.125f));
        d[1] = __uint_as_float(f2tf(v.y * 0.125f));
        d[2] = __uint_as_float(f2tf(v.z * 0.125f));
        d[3] = __uint_as_float(f2tf(v.w * 0.125f));
    }

    float m0r[2] = {-1e30f, -1e30f};
    float lr[2] = {0.0f, 0.0f};
    float O[8][4];
    #pragma unroll
    for (int j = 0; j < 8; j++)
        #pragma unroll
        for (int t = 0; t < 4; t++) O[j][t] = 0.0f;

    const int ra = q0 + warp * 16 + g;   // global q row (c0,c1)
    const int rb = ra + 8;               // global q row (c2,c3)
    const int nkv = 2 * (blockIdx.x + 1);

    for (int kv = 0; kv < nkv; kv++) {
        const int kv0 = kv * 64;
        __syncthreads();
        // load K,V tiles (64x64 each), tf32-rounded
        #pragma unroll
        for (int jj = 0; jj < 4; jj++) {
            int idx = tid + 256 * jj;
            int row = idx >> 4, c4 = (idx & 15) << 2;
            const float* src = base + (size_t)(kv0 + row) * QKV_STRIDE + c4;
            float4 kvec = *(const float4*)(src + D_MODEL);
            float4 vvec = *(const float4*)(src + 2 * D_MODEL);
            float* dk = Ks + row * QS_STR + c4;
            dk[0] = __uint_as_float(f2tf(kvec.x)); dk[1] = __uint_as_float(f2tf(kvec.y));
            dk[2] = __uint_as_float(f2tf(kvec.z)); dk[3] = __uint_as_float(f2tf(kvec.w));
            float* dv = Vs + row * QS_STR + c4;
            dv[0] = __uint_as_float(f2tf(vvec.x)); dv[1] = __uint_as_float(f2tf(vvec.y));
            dv[2] = __uint_as_float(f2tf(vvec.z)); dv[3] = __uint_as_float(f2tf(vvec.w));
        }
        __syncthreads();

        // S = Q K^T  (128x64 per CTA, m16 x n64 per warp)
        float sacc[8][4];
        #pragma unroll
        for (int j = 0; j < 8; j++)
            #pragma unroll
            for (int t = 0; t < 4; t++) sacc[j][t] = 0.0f;
        #pragma unroll
        for (int kk = 0; kk < 64; kk += 8) {
            uint32_t af[4];
            const float* pa = Qs + (warp * 16 + g) * QS_STR + kk + q;
            af[0] = __float_as_uint(pa[0]);
            af[1] = __float_as_uint(pa[8 * QS_STR]);
            af[2] = __float_as_uint(pa[4]);
            af[3] = __float_as_uint(pa[8 * QS_STR + 4]);
            #pragma unroll
            for (int j = 0; j < 8; j++) {
                const float* pb = Ks + (j * 8 + g) * QS_STR + kk + q;
                uint32_t bf[2] = {__float_as_uint(pb[0]), __float_as_uint(pb[4])};
                mma8(sacc[j], af, bf);
            }
        }

        // causal mask (only last two kv tiles can touch the diagonal)
        if (kv >= nkv - 2) {
            #pragma unroll
            for (int j = 0; j < 8; j++) {
                int c0 = kv0 + j * 8 + 2 * q;
                if (c0 > ra)     sacc[j][0] = -1e30f;
                if (c0 + 1 > ra) sacc[j][1] = -1e30f;
                if (c0 > rb)     sacc[j][2] = -1e30f;
                if (c0 + 1 > rb) sacc[j][3] = -1e30f;
            }
        }

        // row max (regs + quad shuffle)
        float mxa = -1e30f, mxb = -1e30f;
        #pragma unroll
        for (int j = 0; j < 8; j++) {
            mxa = fmaxf(mxa, fmaxf(sacc[j][0], sacc[j][1]));
            mxb = fmaxf(mxb, fmaxf(sacc[j][2], sacc[j][3]));
        }
        mxa = fmaxf(mxa, __shfl_xor_sync(0xffffffff, mxa, 1));
        mxa = fmaxf(mxa, __shfl_xor_sync(0xffffffff, mxa, 2));
        mxb = fmaxf(mxb, __shfl_xor_sync(0xffffffff, mxb, 1));
        mxb = fmaxf(mxb, __shfl_xor_sync(0xffffffff, mxb, 2));

        float mna = fmaxf(m0r[0], mxa), mnb = fmaxf(m0r[1], mxb);
        float aa = __expf(m0r[0] - mna), ab = __expf(m0r[1] - mnb);
        m0r[0] = mna; m0r[1] = mnb;

        // exp + P store (tf32) + row sums
        float sa = 0.0f, sb = 0.0f;
        float* prow_a = Ps + (warp * 16 + g) * QS_STR;
        float* prow_b = prow_a + 8 * QS_STR;
        #pragma unroll
        for (int j = 0; j < 8; j++) {
            float p0 = __expf(sacc[j][0] - mna);
            float p1 = __expf(sacc[j][1] - mna);
            float p2 = __expf(sacc[j][2] - mnb);
            float p3 = __expf(sacc[j][3] - mnb);
            sa += p0 + p1; sb += p2 + p3;
            int c = j * 8 + 2 * q;
            prow_a[c]     = __uint_as_float(f2tf(p0));
            prow_a[c + 1] = __uint_as_float(f2tf(p1));
            prow_b[c]     = __uint_as_float(f2tf(p2));
            prow_b[c + 1] = __uint_as_float(f2tf(p3));
        }
        sa += __shfl_xor_sync(0xffffffff, sa, 1);
        sa += __shfl_xor_sync(0xffffffff, sa, 2);
        sb += __shfl_xor_sync(0xffffffff, sb, 1);
        sb += __shfl_xor_sync(0xffffffff, sb, 2);
        lr[0] = lr[0] * aa + sa;
        lr[1] = lr[1] * ab + sb;
        #pragma unroll
        for (int j = 0; j < 8; j++) {
            O[j][0] *= aa; O[j][1] *= aa;
            O[j][2] *= ab; O[j][3] *= ab;
        }
        __syncwarp();   // Ps rows are warp-private; just order store->load

        // O += P @ V  (m16 x n64, k=64)
        #pragma unroll
        for (int kk = 0; kk < 64; kk += 8) {
            uint32_t af[4];
            const float* pa = Ps + (warp * 16 + g) * QS_STR + kk + q;
            af[0] = __float_as_uint(pa[0]);
            af[1] = __float_as_uint(pa[8 * QS_STR]);
            af[2] = __float_as_uint(pa[4]);
            af[3] = __float_as_uint(pa[8 * QS_STR + 4]);
            #pragma unroll
            for (int j = 0; j < 8; j++) {
                const float* pb = Vs + (kk + q) * QS_STR + j * 8 + g;
                uint32_t bf[2] = {__float_as_uint(pb[0]), __float_as_uint(pb[4 * QS_STR])};
                mma8(O[j], af, bf);
            }
        }
    }

    // epilogue: normalize, write [b,t,h*64+d]
    float inva = 1.0f / lr[0], invb = 1.0f / lr[1];
    float* outa = g_attn + ((size_t)b * SEQ + ra) * D_MODEL + h * HEAD_DIM;
    float* outb = g_attn + ((size_t)b * SEQ + rb) * D_MODEL + h * HEAD_DIM;
    #pragma unroll
    for (int j = 0; j < 8; j++) {
        int c = j * 8 + 2 * q;
        *(float2*)(outa + c) = make_float2(O[j][0] * inva, O[j][1] * inva);
        *(float2*)(outb + c) = make_float2(O[j][2] * invb, O[j][3] * invb);
    }
}

// ---------------------------------------------------------------------------
extern "C" void kernel_launch(void* const* d_in, const int* in_sizes, int n_in,
                              void* d_out, int out_size)
{
    (void)in_sizes; (void)n_in; (void)out_size;
    const float* x     = (const float*)d_in[0];
    const float* w_qkv = (const float*)d_in[1];
    const float* b_qkv = (const float*)d_in[2];
    const float* w_out = (const float*)d_in[3];
    const float* b_out = (const float*)d_in[4];
    float* out = (float*)d_out;

    float *qkv, *attn;
    cudaGetSymbolAddress((void**)&qkv, g_qkv);
    cudaGetSymbolAddress((void**)&attn, g_attn);

    cudaFuncSetAttribute(gemm_mma, cudaFuncAttributeMaxDynamicSharedMemorySize, G_SMEM);
    cudaFuncSetAttribute(attn_mma, cudaFuncAttributeMaxDynamicSharedMemorySize, A_SMEM);

    const int M = BATCH * SEQ;  // 8192

    // 1) QKV projection  [8192,1024] x [1024,3072]
    gemm_mma<<<dim3(3 * D_MODEL / 128, M / 128), 128, G_SMEM>>>(
        x, w_qkv, b_qkv, qkv, M, 3 * D_MODEL, D_MODEL);

    // 2) causal flash attention
    attn_mma<<<dim3(SEQ / 128, N_HEADS, BATCH), 256, A_SMEM>>>();

    // 3) output projection  [8192,1024] x [1024,1024]
    gemm_mma<<<dim3(D_MODEL / 128, M / 128), 128, G_SMEM>>>(
        attn, w_out, b_out, out, M, D_MODEL, D_MODEL);
}

// round 5
// speedup vs baseline: 4.2450x; 1.1622x over previous
#include <cuda_runtime.h>
#include <cstdint>
#include <cstddef>

#define D_MODEL 1024
#define N_HEADS 16
#define HEAD_DIM 64
#define BATCH 4
#define SEQ 2048
#define QKV_STRIDE (3 * D_MODEL)

// ------------------------------ scratch ------------------------------------
__device__ float g_qkv[(size_t)BATCH * SEQ * QKV_STRIDE];    // [b,t,3072]
__device__ float g_attn[(size_t)BATCH * SEQ * D_MODEL];      // [b,t,1024]

// ------------------------------ helpers ------------------------------------
__device__ __forceinline__ uint32_t smem_u32(const void* p) {
    uint32_t a;
    asm("{ .reg .u64 t; cvta.to.shared.u64 t, %1; cvt.u32.u64 %0, t; }" : "=r"(a) : "l"(p));
    return a;
}
__device__ __forceinline__ uint32_t f2tf(float x) {
    uint32_t r; asm("cvt.rna.tf32.f32 %0, %1;" : "=r"(r) : "f"(x)); return r;
}
__device__ __forceinline__ void cp16(uint32_t dst, const void* src) {
    asm volatile("cp.async.ca.shared.global [%0], [%1], 16;" :: "r"(dst), "l"(src));
}
#define CP_COMMIT() asm volatile("cp.async.commit_group;" ::: "memory")
#define CP_WAIT0()  asm volatile("cp.async.wait_group 0;" ::: "memory")

// D = A(tf32) * B(tf32) + D ; m16n8k8
__device__ __forceinline__ void mma8(float* c, const uint32_t* a, const uint32_t* b) {
    asm volatile(
        "mma.sync.aligned.m16n8k8.row.col.f32.tf32.tf32.f32 "
        "{%0,%1,%2,%3}, {%4,%5,%6,%7}, {%8,%9}, {%0,%1,%2,%3};"
        : "+f"(c[0]), "+f"(c[1]), "+f"(c[2]), "+f"(c[3])
        : "r"(a[0]), "r"(a[1]), "r"(a[2]), "r"(a[3]), "r"(b[0]), "r"(b[1]));
}

// ------------------------------ tf32 GEMM ----------------------------------
// C[M,N] = A[M,K] @ B[K,N] + bias[N].
// 128x128 CTA tile, BK=32, 256 threads / 8 warps, warp tile m32 x n64 (4x2).
#define AS_STR 36      // 36 mod 32 = 4 -> A-frag lds g*4+q distinct
#define BS_STR 136     // 136 mod 32 = 8 -> B-frag lds q*8+g distinct
#define G_SMEM ((2 * 128 * AS_STR + 2 * 32 * BS_STR) * 4)

__global__ void __launch_bounds__(256, 2) gemm_mma(
    const float* __restrict__ A, const float* __restrict__ B,
    const float* __restrict__ bias, float* __restrict__ C,
    int M, int N, int K)
{
    extern __shared__ float smf[];
    float* As = smf;                       // [2][128][AS_STR]
    float* Bs = smf + 2 * 128 * AS_STR;    // [2][32][BS_STR]

    const int tid = threadIdx.x;
    const int lane = tid & 31, warp = tid >> 5;
    const int g = lane >> 2, q = lane & 3;
    const int wm = (warp >> 1) * 32, wn = (warp & 1) * 64;
    const int m0 = blockIdx.y * 128, n0 = blockIdx.x * 128;

    // loader mapping: A row = tid>>1, 64B chunk; B row = tid>>3, 64B chunk
    const int arow = tid >> 1, akoff = (tid & 1) * 16;
    const int brow = tid >> 3, bcol = (tid & 7) * 16;
    const float* Ag = A + (size_t)(m0 + arow) * K + akoff;
    const float* Bg = B + (size_t)brow * N + n0 + bcol;
    const uint32_t AsA = smem_u32(As) + (arow * AS_STR + akoff) * 4;
    const uint32_t BsA = smem_u32(Bs) + (brow * BS_STR + bcol) * 4;

    float acc[2][8][4];
    #pragma unroll
    for (int i = 0; i < 2; i++)
        #pragma unroll
        for (int j = 0; j < 8; j++)
            #pragma unroll
            for (int t = 0; t < 4; t++) acc[i][j][t] = 0.0f;

    const int nk = K >> 5;

    // prefetch stage 0
    #pragma unroll
    for (int i = 0; i < 4; i++) cp16(AsA + i * 16, Ag + i * 4);
    #pragma unroll
    for (int i = 0; i < 4; i++) cp16(BsA + i * 16, Bg + i * 4);
    CP_COMMIT();

    int buf = 0;
    for (int kt = 0; kt < nk; kt++) {
        CP_WAIT0();
        __syncthreads();
        if (kt + 1 < nk) {
            int s = buf ^ 1;
            const float* ag = Ag + (kt + 1) * 32;
            const float* bg = Bg + (size_t)(kt + 1) * 32 * N;
            uint32_t ad = AsA + s * 128 * AS_STR * 4;
            uint32_t bd = BsA + s * 32 * BS_STR * 4;
            #pragma unroll
            for (int i = 0; i < 4; i++) cp16(ad + i * 16, ag + i * 4);
            #pragma unroll
            for (int i = 0; i < 4; i++) cp16(bd + i * 16, bg + i * 4);
            CP_COMMIT();
        }
        const float* as = As + buf * 128 * AS_STR;
        const float* bs = Bs + buf * 32 * BS_STR;
        #pragma unroll
        for (int kk = 0; kk < 32; kk += 8) {
            uint32_t af[2][4];
            #pragma unroll
            for (int i = 0; i < 2; i++) {
                const float* p = as + (wm + i * 16 + g) * AS_STR + kk + q;
                af[i][0] = f2tf(p[0]);
                af[i][1] = f2tf(p[8 * AS_STR]);
                af[i][2] = f2tf(p[4]);
                af[i][3] = f2tf(p[8 * AS_STR + 4]);
            }
            uint32_t bf[8][2];
            #pragma unroll
            for (int j = 0; j < 8; j++) {
                const float* p = bs + (kk + q) * BS_STR + wn + j * 8 + g;
                bf[j][0] = f2tf(p[0]);
                bf[j][1] = f2tf(p[4 * BS_STR]);
            }
            #pragma unroll
            for (int i = 0; i < 2; i++)
                #pragma unroll
                for (int j = 0; j < 8; j++)
                    mma8(acc[i][j], af[i], bf[j]);
        }
        __syncthreads();
        buf ^= 1;
    }

    // epilogue
    #pragma unroll
    for (int i = 0; i < 2; i++) {
        int row = m0 + wm + i * 16 + g;
        #pragma unroll
        for (int j = 0; j < 8; j++) {
            int col = n0 + wn + j * 8 + 2 * q;
            float b0 = __ldg(&bias[col]), b1 = __ldg(&bias[col + 1]);
            float2 v0 = make_float2(acc[i][j][0] + b0, acc[i][j][1] + b1);
            float2 v1 = make_float2(acc[i][j][2] + b0, acc[i][j][3] + b1);
            *(float2*)(C + (size_t)row * N + col) = v0;
            *(float2*)(C + (size_t)(row + 8) * N + col) = v1;
        }
    }
}

// ------------------------------ attention ----------------------------------
// Flash, BQ=128, BKV=64, 8 warps; warp w owns q-rows [w*16, w*16+16).
// QS_STR = 72: 72 mod 32 = 8 -> all fragment LDS patterns hit 32 distinct banks.
#define QS_STR 72
#define A_SMEM ((128 * QS_STR + 64 * QS_STR + 64 * QS_STR + 128 * QS_STR) * 4)

__global__ void __launch_bounds__(256, 2) attn_mma()
{
    extern __shared__ float smf[];
    float* Qs = smf;                   // [128][72] (pre-scaled, tf32)
    float* Ks = Qs + 128 * QS_STR;     // [64][72]  K[kv][d], tf32
    float* Vs = Ks + 64 * QS_STR;      // [64][72]  V[kv][d], tf32
    float* Ps = Vs + 64 * QS_STR;      // [128][72] P[q][kv], tf32 (warp-private rows)

    const int tid = threadIdx.x;
    const int lane = tid & 31, warp = tid >> 5;
    const int g = lane >> 2, q = lane & 3;
    const int qt = gridDim.x - 1 - blockIdx.x;   // heaviest tiles first
    const int q0 = qt * 128;
    const int h = blockIdx.y, b = blockIdx.z;

    const float* base = g_qkv + (size_t)b * SEQ * QKV_STRIDE + h * HEAD_DIM;

    // load Q tile (scaled by 1/8, tf32-rounded)
    #pragma unroll
    for (int jj = 0; jj < 8; jj++) {
        int idx = tid + 256 * jj;
        int row = idx >> 4, c4 = (idx & 15) << 2;
        float4 v = *(const float4*)(base + (size_t)(q0 + row) * QKV_STRIDE + c4);
        float* d = Qs + row * QS_STR + c4;
        d[0] = __uint_as_float(f2tf(v.x * 0.125f));
        d[1] = __uint_as_float(f2tf(v.y * 0.125f));
        d[2] = __uint_as_float(f2tf(v.z * 0.125f));
        d[3] = __uint_as_float(f2tf(v.w * 0.125f));
    }

    float m0r[2] = {-1e30f, -1e30f};
    float lr[2] = {0.0f, 0.0f};
    float O[8][4];
    #pragma unroll
    for (int j = 0; j < 8; j++)
        #pragma unroll
        for (int t = 0; t < 4; t++) O[j][t] = 0.0f;

    const int ra = q0 + warp * 16 + g;   // global q row (c0,c1)
    const int rb = ra + 8;               // global q row (c2,c3)
    const int nkv = 2 * (qt + 1);

    for (int kv = 0; kv < nkv; kv++) {
        const int kv0 = kv * 64;
        __syncthreads();
        // load K,V tiles (64x64 each), tf32-rounded
        #pragma unroll
        for (int jj = 0; jj < 4; jj++) {
            int idx = tid + 256 * jj;
            int row = idx >> 4, c4 = (idx & 15) << 2;
            const float* src = base + (size_t)(kv0 + row) * QKV_STRIDE + c4;
            float4 kvec = *(const float4*)(src + D_MODEL);
            float4 vvec = *(const float4*)(src + 2 * D_MODEL);
            float* dk = Ks + row * QS_STR + c4;
            dk[0] = __uint_as_float(f2tf(kvec.x)); dk[1] = __uint_as_float(f2tf(kvec.y));
            dk[2] = __uint_as_float(f2tf(kvec.z)); dk[3] = __uint_as_float(f2tf(kvec.w));
            float* dv = Vs + row * QS_STR + c4;
            dv[0] = __uint_as_float(f2tf(vvec.x)); dv[1] = __uint_as_float(f2tf(vvec.y));
            dv[2] = __uint_as_float(f2tf(vvec.z)); dv[3] = __uint_as_float(f2tf(vvec.w));
        }
        __syncthreads();

        // S = Q K^T  (128x64 per CTA, m16 x n64 per warp)
        float sacc[8][4];
        #pragma unroll
        for (int j = 0; j < 8; j++)
            #pragma unroll
            for (int t = 0; t < 4; t++) sacc[j][t] = 0.0f;
        #pragma unroll
        for (int kk = 0; kk < 64; kk += 8) {
            uint32_t af[4];
            const float* pa = Qs + (warp * 16 + g) * QS_STR + kk + q;
            af[0] = __float_as_uint(pa[0]);
            af[1] = __float_as_uint(pa[8 * QS_STR]);
            af[2] = __float_as_uint(pa[4]);
            af[3] = __float_as_uint(pa[8 * QS_STR + 4]);
            #pragma unroll
            for (int j = 0; j < 8; j++) {
                const float* pb = Ks + (j * 8 + g) * QS_STR + kk + q;
                uint32_t bf[2] = {__float_as_uint(pb[0]), __float_as_uint(pb[4])};
                mma8(sacc[j], af, bf);
            }
        }

        // causal mask (only last two kv tiles can touch the diagonal)
        if (kv >= nkv - 2) {
            #pragma unroll
            for (int j = 0; j < 8; j++) {
                int c0 = kv0 + j * 8 + 2 * q;
                if (c0 > ra)     sacc[j][0] = -1e30f;
                if (c0 + 1 > ra) sacc[j][1] = -1e30f;
                if (c0 > rb)     sacc[j][2] = -1e30f;
                if (c0 + 1 > rb) sacc[j][3] = -1e30f;
            }
        }

        // row max (regs + quad shuffle)
        float mxa = -1e30f, mxb = -1e30f;
        #pragma unroll
        for (int j = 0; j < 8; j++) {
            mxa = fmaxf(mxa, fmaxf(sacc[j][0], sacc[j][1]));
            mxb = fmaxf(mxb, fmaxf(sacc[j][2], sacc[j][3]));
        }
        mxa = fmaxf(mxa, __shfl_xor_sync(0xffffffff, mxa, 1));
        mxa = fmaxf(mxa, __shfl_xor_sync(0xffffffff, mxa, 2));
        mxb = fmaxf(mxb, __shfl_xor_sync(0xffffffff, mxb, 1));
        mxb = fmaxf(mxb, __shfl_xor_sync(0xffffffff, mxb, 2));

        float mna = fmaxf(m0r[0], mxa), mnb = fmaxf(m0r[1], mxb);
        float aa = __expf(m0r[0] - mna), ab = __expf(m0r[1] - mnb);
        m0r[0] = mna; m0r[1] = mnb;

        // exp + P store (tf32) + row sums
        float sa = 0.0f, sb = 0.0f;
        float* prow_a = Ps + (warp * 16 + g) * QS_STR;
        float* prow_b = prow_a + 8 * QS_STR;
        #pragma unroll
        for (int j = 0; j < 8; j++) {
            float p0 = __expf(sacc[j][0] - mna);
            float p1 = __expf(sacc[j][1] - mna);
            float p2 = __expf(sacc[j][2] - mnb);
            float p3 = __expf(sacc[j][3] - mnb);
            sa += p0 + p1; sb += p2 + p3;
            int c = j * 8 + 2 * q;
            prow_a[c]     = __uint_as_float(f2tf(p0));
            prow_a[c + 1] = __uint_as_float(f2tf(p1));
            prow_b[c]     = __uint_as_float(f2tf(p2));
            prow_b[c + 1] = __uint_as_float(f2tf(p3));
        }
        sa += __shfl_xor_sync(0xffffffff, sa, 1);
        sa += __shfl_xor_sync(0xffffffff, sa, 2);
        sb += __shfl_xor_sync(0xffffffff, sb, 1);
        sb += __shfl_xor_sync(0xffffffff, sb, 2);
        lr[0] = lr[0] * aa + sa;
        lr[1] = lr[1] * ab + sb;
        #pragma unroll
        for (int j = 0; j < 8; j++) {
            O[j][0] *= aa; O[j][1] *= aa;
            O[j][2] *= ab; O[j][3] *= ab;
        }
        __syncwarp();   // Ps rows are warp-private; just order store->load

        // O += P @ V  (m16 x n64, k=64)
        #pragma unroll
        for (int kk = 0; kk < 64; kk += 8) {
            uint32_t af[4];
            const float* pa = Ps + (warp * 16 + g) * QS_STR + kk + q;
            af[0] = __float_as_uint(pa[0]);
            af[1] = __float_as_uint(pa[8 * QS_STR]);
            af[2] = __float_as_uint(pa[4]);
            af[3] = __float_as_uint(pa[8 * QS_STR + 4]);
            #pragma unroll
            for (int j = 0; j < 8; j++) {
                const float* pb = Vs + (kk + q) * QS_STR + j * 8 + g;
                uint32_t bf[2] = {__float_as_uint(pb[0]), __float_as_uint(pb[4 * QS_STR])};
                mma8(O[j], af, bf);
            }
        }
    }

    // epilogue: normalize, write [b,t,h*64+d]
    float inva = 1.0f / lr[0], invb = 1.0f / lr[1];
    float* outa = g_attn + ((size_t)b * SEQ + ra) * D_MODEL + h * HEAD_DIM;
    float* outb = g_attn + ((size_t)b * SEQ + rb) * D_MODEL + h * HEAD_DIM;
    #pragma unroll
    for (int j = 0; j < 8; j++) {
        int c = j * 8 + 2 * q;
        *(float2*)(outa + c) = make_float2(O[j][0] * inva, O[j][1] * inva);
        *(float2*)(outb + c) = make_float2(O[j][2] * invb, O[j][3] * invb);
    }
}

// ---------------------------------------------------------------------------
extern "C" void kernel_launch(void* const* d_in, const int* in_sizes, int n_in,
                              void* d_out, int out_size)
{
    (void)in_sizes; (void)n_in; (void)out_size;
    const float* x     = (const float*)d_in[0];
    const float* w_qkv = (const float*)d_in[1];
    const float* b_qkv = (const float*)d_in[2];
    const float* w_out = (const float*)d_in[3];
    const float* b_out = (const float*)d_in[4];
    float* out = (float*)d_out;

    float *qkv, *attn;
    cudaGetSymbolAddress((void**)&qkv, g_qkv);
    cudaGetSymbolAddress((void**)&attn, g_attn);

    cudaFuncSetAttribute(gemm_mma, cudaFuncAttributeMaxDynamicSharedMemorySize, G_SMEM);
    cudaFuncSetAttribute(attn_mma, cudaFuncAttributeMaxDynamicSharedMemorySize, A_SMEM);

    const int M = BATCH * SEQ;  // 8192

    // 1) QKV projection  [8192,1024] x [1024,3072]
    gemm_mma<<<dim3(3 * D_MODEL / 128, M / 128), 256, G_SMEM>>>(
        x, w_qkv, b_qkv, qkv, M, 3 * D_MODEL, D_MODEL);

    // 2) causal flash attention
    attn_mma<<<dim3(SEQ / 128, N_HEADS, BATCH), 256, A_SMEM>>>();

    // 3) output projection  [8192,1024] x [1024,1024]
    gemm_mma<<<dim3(D_MODEL / 128, M / 128), 256, G_SMEM>>>(
        attn, w_out, b_out, out, M, D_MODEL, D_MODEL);
}

// round 7
// speedup vs baseline: 5.3787x; 1.2671x over previous
#include <cuda_runtime.h>
#include <cstdint>
#include <cstddef>

#define D_MODEL 1024
#define N_HEADS 16
#define HEAD_DIM 64
#define BATCH 4
#define SEQ 2048
#define QKV_STRIDE (3 * D_MODEL)

// ------------------------------ scratch ------------------------------------
__device__ float g_qkv[(size_t)BATCH * SEQ * QKV_STRIDE];    // [b,t,3072] (tf32, q pre-scaled)
__device__ float g_attn[(size_t)BATCH * SEQ * D_MODEL];      // [b,t,1024] (tf32)
__device__ float g_x32[(size_t)BATCH * SEQ * D_MODEL];       // x, tf32-rounded
__device__ float g_wqkvT[(size_t)3 * D_MODEL * D_MODEL];     // [3072,1024] k-major, tf32
__device__ float g_woT[(size_t)D_MODEL * D_MODEL];           // [1024,1024] k-major, tf32

// ------------------------------ helpers ------------------------------------
__device__ __forceinline__ uint32_t smem_u32(const void* p) {
    uint32_t a;
    asm("{ .reg .u64 t; cvta.to.shared.u64 t, %1; cvt.u32.u64 %0, t; }" : "=r"(a) : "l"(p));
    return a;
}
__device__ __forceinline__ uint32_t f2tf(float x) {
    uint32_t r; asm("cvt.rna.tf32.f32 %0, %1;" : "=r"(r) : "f"(x)); return r;
}
__device__ __forceinline__ void cp16(uint32_t dst, const void* src) {
    asm volatile("cp.async.ca.shared.global [%0], [%1], 16;" :: "r"(dst), "l"(src));
}
#define CP_COMMIT() asm volatile("cp.async.commit_group;" ::: "memory")
#define CP_WAIT0()  asm volatile("cp.async.wait_group 0;" ::: "memory")

__device__ __forceinline__ void ldsm4(uint32_t* r, uint32_t addr) {
    asm volatile("ldmatrix.sync.aligned.m8n8.x4.shared.b16 {%0,%1,%2,%3}, [%4];"
        : "=r"(r[0]), "=r"(r[1]), "=r"(r[2]), "=r"(r[3]) : "r"(addr));
}

// D = A(tf32) * B(tf32) + D ; m16n8k8
__device__ __forceinline__ void mma8(float* c, const uint32_t* a, const uint32_t* b) {
    asm volatile(
        "mma.sync.aligned.m16n8k8.row.col.f32.tf32.tf32.f32 "
        "{%0,%1,%2,%3}, {%4,%5,%6,%7}, {%8,%9}, {%0,%1,%2,%3};"
        : "+f"(c[0]), "+f"(c[1]), "+f"(c[2]), "+f"(c[3])
        : "r"(a[0]), "r"(a[1]), "r"(a[2]), "r"(a[3]), "r"(b[0]), "r"(b[1]));
}

// ------------------------------ init kernels -------------------------------
__global__ void convert_x(const float* __restrict__ in, float* __restrict__ out) {
    size_t i = ((size_t)blockIdx.x * blockDim.x + threadIdx.x) * 4;
    float4 v = *(const float4*)(in + i);
    v.x = __uint_as_float(f2tf(v.x)); v.y = __uint_as_float(f2tf(v.y));
    v.z = __uint_as_float(f2tf(v.z)); v.w = __uint_as_float(f2tf(v.w));
    *(float4*)(out + i) = v;
}

// out[C][R] = tf32(in[R][C])
__global__ void transpose_w(const float* __restrict__ in, float* __restrict__ out,
                            int R, int C) {
    __shared__ float t[32][33];
    int c0 = blockIdx.x * 32, r0 = blockIdx.y * 32;
    #pragma unroll
    for (int j = 0; j < 4; j++) {
        int r = threadIdx.y + j * 8;
        t[r][threadIdx.x] = in[(size_t)(r0 + r) * C + c0 + threadIdx.x];
    }
    __syncthreads();
    #pragma unroll
    for (int j = 0; j < 4; j++) {
        int c = threadIdx.y + j * 8;
        out[(size_t)(c0 + c) * R + r0 + threadIdx.x] =
            __uint_as_float(f2tf(t[threadIdx.x][c]));
    }
}

// ------------------------------ tf32 GEMM ----------------------------------
// C[M,N] = A[M,K] @ BT[N,K]^T + bias[N]. A,BT pre-rounded tf32, k-contiguous.
// 128x128 CTA tile, BK=32, 256 threads / 8 warps, warp tile m32 x n64.
// ROUND: write tf32-rounded bits; cols < qcols additionally scaled by 0.125.
#define TS_STR 36      // 144B rows: 144 mod 128 = 16 -> LDSM rows hit distinct lines
#define G_SMEM ((2 * 128 * TS_STR + 2 * 128 * TS_STR) * 4)

template<bool ROUND>
__global__ void __launch_bounds__(256, 2) gemm_mma(
    const float* __restrict__ A, const float* __restrict__ BT,
    const float* __restrict__ bias, float* __restrict__ C,
    int M, int N, int K, int qcols)
{
    extern __shared__ float smf[];
    float* As = smf;                       // [2][128][TS_STR]
    float* Bs = smf + 2 * 128 * TS_STR;    // [2][128][TS_STR]

    const int tid = threadIdx.x;
    const int lane = tid & 31, warp = tid >> 5;
    const int g = lane >> 2, q = lane & 3;
    const int wm = (warp >> 1) * 32, wn = (warp & 1) * 64;
    const int m0 = blockIdx.y * 128, n0 = blockIdx.x * 128;

    // loaders: 2 threads/row, each 4x16B chunks => 32 floats/row
    const int lrow = tid >> 1, lkoff = (tid & 1) * 16;
    const float* Ag = A + (size_t)(m0 + lrow) * K + lkoff;
    const float* Bg = BT + (size_t)(n0 + lrow) * K + lkoff;
    const uint32_t asU = smem_u32(As), bsU = smem_u32(Bs);
    const uint32_t AsA = asU + (lrow * TS_STR + lkoff) * 4;
    const uint32_t BsA = bsU + (lrow * TS_STR + lkoff) * 4;

    // LDSM per-thread source rows/cols
    const int a_r = ((lane >> 3) & 1) * 8 + (lane & 7);
    const int a_c = ((lane >> 4) & 1) * 4;
    const int b_r = ((lane >> 4) & 1) * 8 + (lane & 7);
    const int b_c = ((lane >> 3) & 1) * 4;
    const uint32_t aoff = ((wm + a_r) * TS_STR + a_c) * 4;
    const uint32_t boff = ((wn + b_r) * TS_STR + b_c) * 4;

    float acc[2][8][4];
    #pragma unroll
    for (int i = 0; i < 2; i++)
        #pragma unroll
        for (int j = 0; j < 8; j++)
            #pragma unroll
            for (int t = 0; t < 4; t++) acc[i][j][t] = 0.0f;

    const int nk = K >> 5;

    // prefetch stage 0
    #pragma unroll
    for (int i = 0; i < 4; i++) cp16(AsA + i * 16, Ag + i * 4);
    #pragma unroll
    for (int i = 0; i < 4; i++) cp16(BsA + i * 16, Bg + i * 4);
    CP_COMMIT();

    int buf = 0;
    for (int kt = 0; kt < nk; kt++) {
        CP_WAIT0();
        __syncthreads();
        if (kt + 1 < nk) {
            int s = buf ^ 1;
            const float* ag = Ag + (kt + 1) * 32;
            const float* bg = Bg + (kt + 1) * 32;
            uint32_t ad = AsA + s * 128 * TS_STR * 4;
            uint32_t bd = BsA + s * 128 * TS_STR * 4;
            #pragma unroll
            for (int i = 0; i < 4; i++) cp16(ad + i * 16, ag + i * 4);
            #pragma unroll
            for (int i = 0; i < 4; i++) cp16(bd + i * 16, bg + i * 4);
            CP_COMMIT();
        }
        const uint32_t aB = asU + buf * 128 * TS_STR * 4 + aoff;
        const uint32_t bB = bsU + buf * 128 * TS_STR * 4 + boff;
        #pragma unroll
        for (int kk = 0; kk < 32; kk += 8) {
            uint32_t af[2][4];
            ldsm4(af[0], aB + kk * 4);
            ldsm4(af[1], aB + kk * 4 + 16 * TS_STR * 4);
            uint32_t bf[4][4];
            #pragma unroll
            for (int jp = 0; jp < 4; jp++)
                ldsm4(bf[jp], bB + kk * 4 + jp * 16 * TS_STR * 4);
            #pragma unroll
            for (int i = 0; i < 2; i++)
                #pragma unroll
                for (int jp = 0; jp < 4; jp++) {
                    mma8(acc[i][2 * jp],     af[i], &bf[jp][0]);
                    mma8(acc[i][2 * jp + 1], af[i], &bf[jp][2]);
                }
        }
        __syncthreads();
        buf ^= 1;
    }

    // epilogue
    #pragma unroll
    for (int i = 0; i < 2; i++) {
        int row = m0 + wm + i * 16 + g;
        #pragma unroll
        for (int j = 0; j < 8; j++) {
            int col = n0 + wn + j * 8 + 2 * q;
            float b0 = __ldg(&bias[col]), b1 = __ldg(&bias[col + 1]);
            float v0 = acc[i][j][0] + b0, v1 = acc[i][j][1] + b1;
            float v2 = acc[i][j][2] + b0, v3 = acc[i][j][3] + b1;
            if (ROUND) {
                float sc = (col < qcols) ? 0.125f : 1.0f;
                v0 = __uint_as_float(f2tf(v0 * sc));
                v1 = __uint_as_float(f2tf(v1 * sc));
                v2 = __uint_as_float(f2tf(v2 * sc));
                v3 = __uint_as_float(f2tf(v3 * sc));
            }
            *(float2*)(C + (size_t)row * N + col) = make_float2(v0, v1);
            *(float2*)(C + (size_t)(row + 8) * N + col) = make_float2(v2, v3);
        }
    }
}

// ------------------------------ attention ----------------------------------
// Flash, BQ=128, BKV=64, 8 warps; warp w owns q-rows [w*16, w*16+16).
// Qs/Ks/Ps stride 68 (272B rows -> LDSM conflict-free); Vs stride 72 (scalar).
#define QS_STR 68
#define VS_STR 72
#define A_SMEM ((128 * QS_STR + 64 * QS_STR + 64 * VS_STR + 128 * QS_STR) * 4)

__global__ void __launch_bounds__(256, 2) attn_mma()
{
    extern __shared__ float smf[];
    float* Qs = smf;                   // [128][68] (pre-scaled tf32)
    float* Ks = Qs + 128 * QS_STR;     // [64][68]
    float* Vs = Ks + 64 * QS_STR;      // [64][72]
    float* Ps = Vs + 64 * VS_STR;      // [128][68] warp-private rows

    const int tid = threadIdx.x;
    const int lane = tid & 31, warp = tid >> 5;
    const int g = lane >> 2, q = lane & 3;
    const int qt = gridDim.x - 1 - blockIdx.x;   // heaviest tiles first
    const int q0 = qt * 128;
    const int h = blockIdx.y, b = blockIdx.z;

    const float* base = g_qkv + (size_t)b * SEQ * QKV_STRIDE + h * HEAD_DIM;
    const uint32_t qsU = smem_u32(Qs), ksU = smem_u32(Ks);
    const uint32_t vsU = smem_u32(Vs), psU = smem_u32(Ps);

    // LDSM per-thread source rows/cols
    const int a_r = ((lane >> 3) & 1) * 8 + (lane & 7);
    const int a_c = ((lane >> 4) & 1) * 4;
    const int b_r = ((lane >> 4) & 1) * 8 + (lane & 7);
    const int b_c = ((lane >> 3) & 1) * 4;
    const uint32_t aoffQ = ((warp * 16 + a_r) * QS_STR + a_c) * 4;
    const uint32_t boffK = (b_r * QS_STR + b_c) * 4;

    // load Q tile (cp.async; data already tf32 + pre-scaled)
    #pragma unroll
    for (int jj = 0; jj < 8; jj++) {
        int idx = tid + 256 * jj;
        int row = idx >> 4, c4 = (idx & 15) << 2;
        cp16(qsU + (row * QS_STR + c4) * 4, base + (size_t)(q0 + row) * QKV_STRIDE + c4);
    }
    CP_COMMIT();

    float m0r[2] = {-1e30f, -1e30f};
    float lr[2] = {0.0f, 0.0f};
    float O[8][4];
    #pragma unroll
    for (int j = 0; j < 8; j++)
        #pragma unroll
        for (int t = 0; t < 4; t++) O[j][t] = 0.0f;

    const int ra = q0 + warp * 16 + g;
    const int rb = ra + 8;
    const int nkv = 2 * (qt + 1);

    for (int kv = 0; kv < nkv; kv++) {
        const int kv0 = kv * 64;
        __syncthreads();
        // load K,V tiles via cp.async
        #pragma unroll
        for (int jj = 0; jj < 4; jj++) {
            int idx = tid + 256 * jj;
            int row = idx >> 4, c4 = (idx & 15) << 2;
            const float* src = base + (size_t)(kv0 + row) * QKV_STRIDE + c4;
            cp16(ksU + (row * QS_STR + c4) * 4, src + D_MODEL);
            cp16(vsU + (row * VS_STR + c4) * 4, src + 2 * D_MODEL);
        }
        CP_COMMIT();
        CP_WAIT0();
        __syncthreads();

        // S = Q K^T  (m16 x n64 per warp, k=64)
        float sacc[8][4];
        #pragma unroll
        for (int j = 0; j < 8; j++)
            #pragma unroll
            for (int t = 0; t < 4; t++) sacc[j][t] = 0.0f;
        #pragma unroll
        for (int kk = 0; kk < 64; kk += 8) {
            uint32_t af[4];
            ldsm4(af, qsU + aoffQ + kk * 4);
            uint32_t bf[4][4];
            #pragma unroll
            for (int jp = 0; jp < 4; jp++)
                ldsm4(bf[jp], ksU + boffK + kk * 4 + jp * 16 * QS_STR * 4);
            #pragma unroll
            for (int jp = 0; jp < 4; jp++) {
                mma8(sacc[2 * jp],     af, &bf[jp][0]);
                mma8(sacc[2 * jp + 1], af, &bf[jp][2]);
            }
        }

        // causal mask
        if (kv >= nkv - 2) {
            #pragma unroll
            for (int j = 0; j < 8; j++) {
                int c0 = kv0 + j * 8 + 2 * q;
                if (c0 > ra)     sacc[j][0] = -1e30f;
                if (c0 + 1 > ra) sacc[j][1] = -1e30f;
                if (c0 > rb)     sacc[j][2] = -1e30f;
                if (c0 + 1 > rb) sacc[j][3] = -1e30f;
            }
        }

        // row max
        float mxa = -1e30f, mxb = -1e30f;
        #pragma unroll
        for (int j = 0; j < 8; j++) {
            mxa = fmaxf(mxa, fmaxf(sacc[j][0], sacc[j][1]));
            mxb = fmaxf(mxb, fmaxf(sacc[j][2], sacc[j][3]));
        }
        mxa = fmaxf(mxa, __shfl_xor_sync(0xffffffff, mxa, 1));
        mxa = fmaxf(mxa, __shfl_xor_sync(0xffffffff, mxa, 2));
        mxb = fmaxf(mxb, __shfl_xor_sync(0xffffffff, mxb, 1));
        mxb = fmaxf(mxb, __shfl_xor_sync(0xffffffff, mxb, 2));

        float mna = fmaxf(m0r[0], mxa), mnb = fmaxf(m0r[1], mxb);
        float aa = __expf(m0r[0] - mna), ab = __expf(m0r[1] - mnb);
        m0r[0] = mna; m0r[1] = mnb;

        // exp + P store (tf32) + row sums
        float sa = 0.0f, sb = 0.0f;
        float* prow_a = Ps + (warp * 16 + g) * QS_STR;
        float* prow_b = prow_a + 8 * QS_STR;
        #pragma unroll
        for (int j = 0; j < 8; j++) {
            float p0 = __expf(sacc[j][0] - mna);
            float p1 = __expf(sacc[j][1] - mna);
            float p2 = __expf(sacc[j][2] - mnb);
            float p3 = __expf(sacc[j][3] - mnb);
            sa += p0 + p1; sb += p2 + p3;
            int c = j * 8 + 2 * q;
            prow_a[c]     = __uint_as_float(f2tf(p0));
            prow_a[c + 1] = __uint_as_float(f2tf(p1));
            prow_b[c]     = __uint_as_float(f2tf(p2));
            prow_b[c + 1] = __uint_as_float(f2tf(p3));
        }
        sa += __shfl_xor_sync(0xffffffff, sa, 1);
        sa += __shfl_xor_sync(0xffffffff, sa, 2);
        sb += __shfl_xor_sync(0xffffffff, sb, 1);
        sb += __shfl_xor_sync(0xffffffff, sb, 2);
        lr[0] = lr[0] * aa + sa;
        lr[1] = lr[1] * ab + sb;
        #pragma unroll
        for (int j = 0; j < 8; j++) {
            O[j][0] *= aa; O[j][1] *= aa;
            O[j][2] *= ab; O[j][3] *= ab;
        }
        __syncwarp();   // order Ps stores -> ldmatrix (warp-private rows)

        // O += P @ V  (m16 x n64, k=64); V fragment scalar (transposed orient.)
        #pragma unroll
        for (int kk = 0; kk < 64; kk += 8) {
            uint32_t af[4];
            ldsm4(af, psU + aoffQ + kk * 4);
            #pragma unroll
            for (int j = 0; j < 8; j++) {
                const float* pb = Vs + (kk + q) * VS_STR + j * 8 + g;
                uint32_t bf[2] = {__float_as_uint(pb[0]), __float_as_uint(pb[4 * VS_STR])};
                mma8(O[j], af, bf);
            }
        }
    }

    // epilogue: normalize, round to tf32, write [b,t,h*64+d]
    float inva = 1.0f / lr[0], invb = 1.0f / lr[1];
    float* outa = g_attn + ((size_t)b * SEQ + ra) * D_MODEL + h * HEAD_DIM;
    float* outb = g_attn + ((size_t)b * SEQ + rb) * D_MODEL + h * HEAD_DIM;
    #pragma unroll
    for (int j = 0; j < 8; j++) {
        int c = j * 8 + 2 * q;
        *(float2*)(outa + c) = make_float2(__uint_as_float(f2tf(O[j][0] * inva)),
                                           __uint_as_float(f2tf(O[j][1] * inva)));
        *(float2*)(outb + c) = make_float2(__uint_as_float(f2tf(O[j][2] * invb)),
                                           __uint_as_float(f2tf(O[j][3] * invb)));
    }
}

// ---------------------------------------------------------------------------
extern "C" void kernel_launch(void* const* d_in, const int* in_sizes, int n_in,
                              void* d_out, int out_size)
{
    (void)in_sizes; (void)n_in; (void)out_size;
    const float* x     = (const float*)d_in[0];
    const float* w_qkv = (const float*)d_in[1];
    const float* b_qkv = (const float*)d_in[2];
    const float* w_out = (const float*)d_in[3];
    const float* b_out = (const float*)d_in[4];
    float* out = (float*)d_out;

    float *qkv, *attn, *x32, *wqkvT, *woT;
    cudaGetSymbolAddress((void**)&qkv, g_qkv);
    cudaGetSymbolAddress((void**)&attn, g_attn);
    cudaGetSymbolAddress((void**)&x32, g_x32);
    cudaGetSymbolAddress((void**)&wqkvT, g_wqkvT);
    cudaGetSymbolAddress((void**)&woT, g_woT);

    cudaFuncSetAttribute(gemm_mma<true>,  cudaFuncAttributeMaxDynamicSharedMemorySize, G_SMEM);
    cudaFuncSetAttribute(gemm_mma<false>, cudaFuncAttributeMaxDynamicSharedMemorySize, G_SMEM);
    cudaFuncSetAttribute(attn_mma, cudaFuncAttributeMaxDynamicSharedMemorySize, A_SMEM);

    const int M = BATCH * SEQ;  // 8192

    // init: tf32-round x, transpose+round weights
    convert_x<<<(M * D_MODEL) / (256 * 4), 256>>>(x, x32);
    transpose_w<<<dim3(3 * D_MODEL / 32, D_MODEL / 32), dim3(32, 8)>>>(w_qkv, wqkvT, D_MODEL, 3 * D_MODEL);
    transpose_w<<<dim3(D_MODEL / 32, D_MODEL / 32), dim3(32, 8)>>>(w_out, woT, D_MODEL, D_MODEL);

    // 1) QKV projection (writes tf32, q-cols pre-scaled by 0.125)
    gemm_mma<true><<<dim3(3 * D_MODEL / 128, M / 128), 256, G_SMEM>>>(
        x32, wqkvT, b_qkv, qkv, M, 3 * D_MODEL, D_MODEL, D_MODEL);

    // 2) causal flash attention
    attn_mma<<<dim3(SEQ / 128, N_HEADS, BATCH), 256, A_SMEM>>>();

    // 3) output projection (full fp32 out)
    gemm_mma<false><<<dim3(D_MODEL / 128, M / 128), 256, G_SMEM>>>(
        attn, woT, b_out, out, M, D_MODEL, D_MODEL, 0);
}